// round 1
// baseline (speedup 1.0000x reference)
#include <cuda_runtime.h>

#define NN      65536
#define EE      1048576
#define IN_DIM  500
#define HID     256
#define OUTD    64
#define ALPHA   0.1f

// ---------------- static device scratch (no allocations allowed) ----------------
__device__ float g_h1[(size_t)NN * HID];   // after layer 1
__device__ float g_h2[(size_t)NN * HID];   // after layer 2
__device__ float g_h0[(size_t)NN * OUTD];  // after layer 3 (h0)
__device__ float g_hA[(size_t)NN * OUTD];  // ping
__device__ float g_hB[(size_t)NN * OUTD];  // pong
__device__ int   g_rowoff[NN + 1];
__device__ int   g_cursor[NN];
__device__ int   g_ecol[EE];
__device__ float g_ew[EE];

// ---------------- CSR construction ----------------
__global__ void zero_cursor_kernel() {
    int i = blockIdx.x * blockDim.x + threadIdx.x;
    if (i < NN) g_cursor[i] = 0;
}

__global__ void hist_kernel(const int* __restrict__ row) {
    int e = blockIdx.x * blockDim.x + threadIdx.x;
    if (e < EE) atomicAdd(&g_cursor[row[e]], 1);
}

// Single-block exclusive scan of degrees (65536 = 1024 threads x 64 elems).
__global__ void scan_kernel() {
    __shared__ int s[1024];
    int t = threadIdx.x;
    int base = t * 64;
    int sum = 0;
#pragma unroll 8
    for (int i = 0; i < 64; i++) sum += g_cursor[base + i];
    s[t] = sum;
    __syncthreads();
    // inclusive Hillis-Steele scan over 1024 chunk sums
    for (int off = 1; off < 1024; off <<= 1) {
        int v = (t >= off) ? s[t - off] : 0;
        __syncthreads();
        s[t] += v;
        __syncthreads();
    }
    int running = s[t] - sum;  // exclusive prefix for this chunk
    for (int i = 0; i < 64; i++) {
        int d = g_cursor[base + i];
        g_rowoff[base + i] = running;
        g_cursor[base + i] = running;  // scatter cursor
        running += d;
    }
    if (t == 1023) g_rowoff[NN] = s[1023];
}

__global__ void scatter_kernel(const int* __restrict__ row,
                               const int* __restrict__ col,
                               const float* __restrict__ w) {
    int e = blockIdx.x * blockDim.x + threadIdx.x;
    if (e < EE) {
        int p = atomicAdd(&g_cursor[row[e]], 1);
        g_ecol[p] = col[e];
        g_ew[p]   = w[e];
    }
}

// ---------------- fp32 tiled GEMM with fused bias (+ optional ReLU) ----------------
// C[M,N] = A[M,K] @ B[K,N] + bias[N]   (all row-major)
// BM=128, BN=64, BK=16, 256 threads, 8x4 micro-tile per thread.
template <bool RELU>
__global__ void __launch_bounds__(256) gemm_bias_kernel(
    const float* __restrict__ A, const float* __restrict__ B,
    const float* __restrict__ bias, float* __restrict__ C,
    int M, int N, int K)
{
    const int BM = 128, BN = 64, BK = 16;
    __shared__ float As[BK][BM];   // transposed A tile
    __shared__ float Bs[BK][BN];

    int tid = threadIdx.x;
    int m0 = blockIdx.x * BM;
    int n0 = blockIdx.y * BN;
    int ty = tid >> 4;     // 0..15 -> rows ty*8 .. ty*8+7
    int tx = tid & 15;     // 0..15 -> cols tx*4 .. tx*4+3

    float acc[8][4];
#pragma unroll
    for (int i = 0; i < 8; i++)
#pragma unroll
        for (int j = 0; j < 4; j++) acc[i][j] = 0.f;

    int nt = (K + BK - 1) / BK;
    for (int t = 0; t < nt; t++) {
        int k0 = t * BK;
        // ---- load A tile (2 float4 per thread), store transposed ----
#pragma unroll
        for (int sl = 0; sl < 2; sl++) {
            int slot = tid + sl * 256;       // 0..511
            int row = slot >> 2;             // 0..127
            int kq  = slot & 3;              // 0..3 -> k chunk of 4
            int kg  = k0 + kq * 4;
            float4 av;
            if (kg + 3 < K) {
                av = *(const float4*)(A + (size_t)(m0 + row) * K + kg);
            } else {
                float tmp[4] = {0.f, 0.f, 0.f, 0.f};
#pragma unroll
                for (int i = 0; i < 4; i++)
                    if (kg + i < K) tmp[i] = A[(size_t)(m0 + row) * K + kg + i];
                av = make_float4(tmp[0], tmp[1], tmp[2], tmp[3]);
            }
            As[kq * 4 + 0][row] = av.x;
            As[kq * 4 + 1][row] = av.y;
            As[kq * 4 + 2][row] = av.z;
            As[kq * 4 + 3][row] = av.w;
        }
        // ---- load B tile (1 float4 per thread) ----
        {
            int brow = tid >> 4;             // 0..15
            int bc   = (tid & 15) * 4;       // 0..60
            int kg = k0 + brow;
            float4 bv = make_float4(0.f, 0.f, 0.f, 0.f);
            if (kg < K) bv = *(const float4*)(B + (size_t)kg * N + n0 + bc);
            *(float4*)&Bs[brow][bc] = bv;
        }
        __syncthreads();

#pragma unroll
        for (int kk = 0; kk < BK; kk++) {
            float a[8], b[4];
            *(float4*)&a[0] = *(const float4*)&As[kk][ty * 8];
            *(float4*)&a[4] = *(const float4*)&As[kk][ty * 8 + 4];
            *(float4*)&b[0] = *(const float4*)&Bs[kk][tx * 4];
#pragma unroll
            for (int i = 0; i < 8; i++)
#pragma unroll
                for (int j = 0; j < 4; j++)
                    acc[i][j] += a[i] * b[j];
        }
        __syncthreads();
    }

    // ---- epilogue: bias (+relu), vectorized store ----
    float4 bv = *(const float4*)(bias + n0 + tx * 4);
#pragma unroll
    for (int i = 0; i < 8; i++) {
        int m = m0 + ty * 8 + i;
        float4 v;
        v.x = acc[i][0] + bv.x;
        v.y = acc[i][1] + bv.y;
        v.z = acc[i][2] + bv.z;
        v.w = acc[i][3] + bv.w;
        if (RELU) {
            v.x = fmaxf(v.x, 0.f); v.y = fmaxf(v.y, 0.f);
            v.z = fmaxf(v.z, 0.f); v.w = fmaxf(v.w, 0.f);
        }
        *(float4*)(C + (size_t)m * N + n0 + tx * 4) = v;
    }
}

// ---------------- propagation: one warp per row, atomic-free segment sum ----------------
// hdst[r] = 0.9 * sum_{e in row r} hsrc[col(e)] * w(e) + 0.1 * h0[r]
__global__ void __launch_bounds__(256) prop_kernel(
    const float* __restrict__ hsrc, const float* __restrict__ h0,
    float* __restrict__ hdst)
{
    int warp = (blockIdx.x * blockDim.x + threadIdx.x) >> 5;
    if (warp >= NN) return;
    int lane = threadIdx.x & 31;

    int beg = g_rowoff[warp];
    int end = g_rowoff[warp + 1];

    float2 acc = make_float2(0.f, 0.f);
    for (int e = beg; e < end; e += 32) {
        int idx = e + lane;
        int c = 0; float w = 0.f;
        if (idx < end) { c = g_ecol[idx]; w = g_ew[idx]; }
        int cnt = min(32, end - e);
        for (int j = 0; j < cnt; j++) {
            int   cc = __shfl_sync(0xffffffffu, c, j);
            float ww = __shfl_sync(0xffffffffu, w, j);
            float2 hv = *(const float2*)(hsrc + (size_t)cc * OUTD + lane * 2);
            acc.x = fmaf(hv.x, ww, acc.x);
            acc.y = fmaf(hv.y, ww, acc.y);
        }
    }
    float2 h0v = *(const float2*)(h0 + (size_t)warp * OUTD + lane * 2);
    float2 outv;
    outv.x = (1.0f - ALPHA) * acc.x + ALPHA * h0v.x;
    outv.y = (1.0f - ALPHA) * acc.y + ALPHA * h0v.y;
    *(float2*)(hdst + (size_t)warp * OUTD + lane * 2) = outv;
}

// ---------------- host launcher ----------------
extern "C" void kernel_launch(void* const* d_in, const int* in_sizes, int n_in,
                              void* d_out, int out_size)
{
    const float* x    = (const float*)d_in[0];
    const float* W1   = (const float*)d_in[1];
    const float* b1   = (const float*)d_in[2];
    const float* W2   = (const float*)d_in[3];
    const float* b2   = (const float*)d_in[4];
    const float* W3   = (const float*)d_in[5];
    const float* b3   = (const float*)d_in[6];
    const float* ew   = (const float*)d_in[7];
    const int*   erow = (const int*)d_in[8];
    const int*   ecol = (const int*)d_in[9];

    float *h1, *h2, *h0, *hA, *hB;
    cudaGetSymbolAddress((void**)&h1, g_h1);
    cudaGetSymbolAddress((void**)&h2, g_h2);
    cudaGetSymbolAddress((void**)&h0, g_h0);
    cudaGetSymbolAddress((void**)&hA, g_hA);
    cudaGetSymbolAddress((void**)&hB, g_hB);

    // CSR build
    zero_cursor_kernel<<<NN / 256, 256>>>();
    hist_kernel<<<EE / 256, 256>>>(erow);
    scan_kernel<<<1, 1024>>>();
    scatter_kernel<<<EE / 256, 256>>>(erow, ecol, ew);

    // MLP
    gemm_bias_kernel<true ><<<dim3(NN / 128, HID / 64), 256>>>(x,  W1, b1, h1, NN, HID,  IN_DIM);
    gemm_bias_kernel<true ><<<dim3(NN / 128, HID / 64), 256>>>(h1, W2, b2, h2, NN, HID,  HID);
    gemm_bias_kernel<false><<<dim3(NN / 128, OUTD / 64), 256>>>(h2, W3, b3, h0, NN, OUTD, HID);

    // K=10 propagation steps, final step writes directly to d_out
    float* out = (float*)d_out;
    const float* src = h0;
    for (int s = 0; s < 10; s++) {
        float* dst = (s == 9) ? out : ((s & 1) ? hB : hA);
        prop_kernel<<<(NN * 32) / 256, 256>>>(src, h0, dst);
        src = dst;
    }
}

// round 3
// speedup vs baseline: 1.5898x; 1.5898x over previous
#include <cuda_runtime.h>
#include <cuda_bf16.h>
#include <cstdint>

#define NN      65536
#define EE      1048576
#define IN_DIM  500
#define KPAD1   512
#define HID     256
#define OUTD    64
#define ALPHA   0.1f

// ---------------- static device scratch ----------------
__device__ float g_h1[(size_t)NN * HID];
__device__ float g_h2[(size_t)NN * HID];
__device__ float g_h0[(size_t)NN * OUTD];
__device__ float g_hA[(size_t)NN * OUTD];
__device__ float g_hB[(size_t)NN * OUTD];
__device__ __nv_bfloat16 g_B1h[(size_t)HID * KPAD1];
__device__ __nv_bfloat16 g_B1l[(size_t)HID * KPAD1];
__device__ __nv_bfloat16 g_B2h[(size_t)HID * HID];
__device__ __nv_bfloat16 g_B2l[(size_t)HID * HID];
__device__ __nv_bfloat16 g_B3h[(size_t)OUTD * HID];
__device__ __nv_bfloat16 g_B3l[(size_t)OUTD * HID];
__device__ int   g_rowoff[NN + 1];
__device__ int   g_cursor[NN];
__device__ int   g_ecol[EE];
__device__ float g_ew[EE];

// ---------------- helpers ----------------
__device__ __forceinline__ uint32_t smem_to_u32(const void* p) {
    uint32_t a;
    asm("{ .reg .u64 t; cvta.to.shared.u64 t, %1; cvt.u32.u64 %0, t; }" : "=r"(a) : "l"(p));
    return a;
}

__device__ __forceinline__ void ldmatrix_x4(uint32_t* r, uint32_t addr) {
    asm volatile("ldmatrix.sync.aligned.m8n8.x4.shared.b16 {%0,%1,%2,%3}, [%4];"
                 : "=r"(r[0]), "=r"(r[1]), "=r"(r[2]), "=r"(r[3]) : "r"(addr));
}

__device__ __forceinline__ void mma_bf16(float* c, const uint32_t* a, const uint32_t* b) {
    asm volatile(
        "mma.sync.aligned.m16n8k16.row.col.f32.bf16.bf16.f32 "
        "{%0,%1,%2,%3}, {%4,%5,%6,%7}, {%8,%9}, {%0,%1,%2,%3};"
        : "+f"(c[0]), "+f"(c[1]), "+f"(c[2]), "+f"(c[3])
        : "r"(a[0]), "r"(a[1]), "r"(a[2]), "r"(a[3]), "r"(b[0]), "r"(b[1]));
}

__device__ __forceinline__ void split_bf16(float a, __nv_bfloat16& hi, __nv_bfloat16& lo) {
    hi = __float2bfloat16_rn(a);
    lo = __float2bfloat16_rn(a - __bfloat162float(hi));
}
__device__ __forceinline__ uint32_t pack_bf16(__nv_bfloat16 x0, __nv_bfloat16 x1) {
    return ((uint32_t)__bfloat16_as_ushort(x1) << 16) | (uint32_t)__bfloat16_as_ushort(x0);
}

// ---------------- CSR construction ----------------
__global__ void zero_cursor_kernel() {
    int i = blockIdx.x * blockDim.x + threadIdx.x;
    if (i < NN) g_cursor[i] = 0;
}
__global__ void hist_kernel(const int* __restrict__ row) {
    int e = blockIdx.x * blockDim.x + threadIdx.x;
    if (e < EE) atomicAdd(&g_cursor[row[e]], 1);
}
__global__ void scan_kernel() {
    __shared__ int s[1024];
    int t = threadIdx.x;
    int base = t * 64;
    int sum = 0;
#pragma unroll 8
    for (int i = 0; i < 64; i++) sum += g_cursor[base + i];
    s[t] = sum;
    __syncthreads();
    for (int off = 1; off < 1024; off <<= 1) {
        int v = (t >= off) ? s[t - off] : 0;
        __syncthreads();
        s[t] += v;
        __syncthreads();
    }
    int running = s[t] - sum;
    for (int i = 0; i < 64; i++) {
        int d = g_cursor[base + i];
        g_rowoff[base + i] = running;
        g_cursor[base + i] = running;
        running += d;
    }
    if (t == 1023) g_rowoff[NN] = s[1023];
}
__global__ void scatter_kernel(const int* __restrict__ row, const int* __restrict__ col,
                               const float* __restrict__ w) {
    int e = blockIdx.x * blockDim.x + threadIdx.x;
    if (e < EE) {
        int p = atomicAdd(&g_cursor[row[e]], 1);
        g_ecol[p] = col[e];
        g_ew[p]   = w[e];
    }
}

// ---------------- weight transpose + pad + bf16 split ----------------
// Bh/Bl[n][k] = split(W[k][n]), zeros for k >= K.
__global__ void splitw_kernel(const float* __restrict__ W,
                              __nv_bfloat16* __restrict__ Bh, __nv_bfloat16* __restrict__ Bl,
                              int K, int N, int Kpad) {
    int idx = blockIdx.x * blockDim.x + threadIdx.x;
    if (idx >= N * Kpad) return;
    int n = idx / Kpad, k = idx - n * Kpad;
    float v = (k < K) ? W[(size_t)k * N + n] : 0.f;
    __nv_bfloat16 hi, lo;
    split_bf16(v, hi, lo);
    Bh[idx] = hi;
    Bl[idx] = lo;
}

// ---------------- bf16-split mma.sync GEMM ----------------
// C[M,N_] = A[M,K] @ W + bias, with W pre-split K-major in Bh/Bl [N_][Kpad].
// CTA tile 128x64, BK=32, 8 warps in 4(m) x 2(n), warp tile 32x32.
// smem layout (per buffer): Ah(128x40 bf16) Al Bh(64x40) Bl, stride 40 halves.
#define SM_AH   0
#define SM_AL   10240
#define SM_BH   20480
#define SM_BL   25600
#define SM_BUF  30720
#define GEMM_SMEM (2 * SM_BUF)

template <int N_, bool RELU>
__global__ void __launch_bounds__(256, 1) gemm_mma_kernel(
    const float* __restrict__ A, const __nv_bfloat16* __restrict__ Bh,
    const __nv_bfloat16* __restrict__ Bl, const float* __restrict__ bias,
    float* __restrict__ C, int K, int Kpad)
{
    extern __shared__ char smem[];
    uint32_t sbase = smem_to_u32(smem);

    int tid  = threadIdx.x;
    int wid  = tid >> 5;
    int lane = tid & 31;
    int m0 = blockIdx.x * 128;
    int n0 = blockIdx.y * 64;
    int warp_m = wid & 3;     // 0..3 -> m offset *32
    int warp_n = wid >> 2;    // 0..1 -> n offset *32

    float acc[2][4][4];
#pragma unroll
    for (int i = 0; i < 2; i++)
#pragma unroll
        for (int j = 0; j < 4; j++)
#pragma unroll
            for (int r = 0; r < 4; r++) acc[i][j][r] = 0.f;

    const int nch = Kpad >> 5;

    // global staging regs
    float4 ga[4];
    uint4  gbh, gbl;

    // A-load indices (per thread): 4 float4 slots covering 128x32
    int a_row[4], a_col[4];
#pragma unroll
    for (int i = 0; i < 4; i++) {
        int slot = tid + i * 256;
        a_row[i] = slot >> 3;
        a_col[i] = (slot & 7) * 4;
    }
    int b_row = tid >> 2;        // 0..63
    int b_seg = tid & 3;         // 0..3, 8 halves each

#define LOAD_GLOBAL(CH) do { \
    int k0_ = (CH) << 5; \
    _Pragma("unroll") \
    for (int i = 0; i < 4; i++) { \
        int kg = k0_ + a_col[i]; \
        if (kg < K) ga[i] = *(const float4*)(A + (size_t)(m0 + a_row[i]) * K + kg); \
        else        ga[i] = make_float4(0.f, 0.f, 0.f, 0.f); \
    } \
    { \
        const __nv_bfloat16* ph = Bh + (size_t)(n0 + b_row) * Kpad + k0_ + b_seg * 8; \
        const __nv_bfloat16* pl = Bl + (size_t)(n0 + b_row) * Kpad + k0_ + b_seg * 8; \
        gbh = *(const uint4*)ph; \
        gbl = *(const uint4*)pl; \
    } \
} while (0)

#define STORE_SMEM(BUF) do { \
    char* tb = smem + (BUF) * SM_BUF; \
    _Pragma("unroll") \
    for (int i = 0; i < 4; i++) { \
        __nv_bfloat16 hx, lx, hy, ly, hz, lz, hw, lw; \
        split_bf16(ga[i].x, hx, lx); split_bf16(ga[i].y, hy, ly); \
        split_bf16(ga[i].z, hz, lz); split_bf16(ga[i].w, hw, lw); \
        uint2 ph_ = make_uint2(pack_bf16(hx, hy), pack_bf16(hz, hw)); \
        uint2 pl_ = make_uint2(pack_bf16(lx, ly), pack_bf16(lz, lw)); \
        int off = a_row[i] * 80 + a_col[i] * 2; \
        *(uint2*)(tb + SM_AH + off) = ph_; \
        *(uint2*)(tb + SM_AL + off) = pl_; \
    } \
    { \
        int off = b_row * 80 + b_seg * 16; \
        *(uint4*)(tb + SM_BH + off) = gbh; \
        *(uint4*)(tb + SM_BL + off) = gbl; \
    } \
} while (0)

    LOAD_GLOBAL(0);
    STORE_SMEM(0);
    __syncthreads();

    for (int ch = 0; ch < nch; ch++) {
        if (ch + 1 < nch) LOAD_GLOBAL(ch + 1);

        // ---- compute from buffer ch&1 ----
        uint32_t ub = sbase + (ch & 1) * SM_BUF;
#pragma unroll
        for (int kk = 0; kk < 32; kk += 16) {
            uint32_t afr[2][2][4];   // [split][mtile]
            uint32_t bfr[2][2][4];   // [split][npair]
            {
                int rowA = warp_m * 32 + (lane & 15);
                int colA = kk + ((lane >> 4) << 3);
#pragma unroll
                for (int mt = 0; mt < 2; mt++) {
                    uint32_t ad = ub + (uint32_t)((rowA + mt * 16) * 80 + colA * 2);
                    ldmatrix_x4(afr[0][mt], ad + SM_AH);
                    ldmatrix_x4(afr[1][mt], ad + SM_AL);
                }
                int rowB = warp_n * 32 + ((lane >> 4) << 3) + (lane & 7);
                int colB = kk + (((lane >> 3) & 1) << 3);
#pragma unroll
                for (int np = 0; np < 2; np++) {
                    uint32_t bd = ub + (uint32_t)((rowB + np * 16) * 80 + colB * 2);
                    ldmatrix_x4(bfr[0][np], bd + SM_BH);
                    ldmatrix_x4(bfr[1][np], bd + SM_BL);
                }
            }
#pragma unroll
            for (int mt = 0; mt < 2; mt++)
#pragma unroll
                for (int nt = 0; nt < 4; nt++) {
                    int np = nt >> 1, sub = (nt & 1) * 2;
                    mma_bf16(acc[mt][nt], afr[0][mt], &bfr[0][np][sub]);  // hi*hi
                    mma_bf16(acc[mt][nt], afr[0][mt], &bfr[1][np][sub]);  // hi*lo
                    mma_bf16(acc[mt][nt], afr[1][mt], &bfr[0][np][sub]);  // lo*hi
                }
        }
        __syncthreads();
        if (ch + 1 < nch) {
            STORE_SMEM((ch + 1) & 1);
        }
        __syncthreads();
    }

    // ---- epilogue ----
    int rb   = m0 + warp_m * 32 + (lane >> 2);
    int colb = n0 + warp_n * 32 + (lane & 3) * 2;
#pragma unroll
    for (int mt = 0; mt < 2; mt++)
#pragma unroll
        for (int nt = 0; nt < 4; nt++)
#pragma unroll
            for (int r = 0; r < 4; r++) {
                int row = rb + mt * 16 + ((r >> 1) << 3);
                int col = colb + nt * 8 + (r & 1);
                float v = acc[mt][nt][r] + __ldg(bias + col);
                if (RELU) v = fmaxf(v, 0.f);
                C[(size_t)row * N_ + col] = v;
            }
}

// ---------------- propagation ----------------
__global__ void __launch_bounds__(256) prop_kernel(
    const float* __restrict__ hsrc, const float* __restrict__ h0,
    float* __restrict__ hdst)
{
    int warp = (blockIdx.x * blockDim.x + threadIdx.x) >> 5;
    if (warp >= NN) return;
    int lane = threadIdx.x & 31;

    int beg = g_rowoff[warp];
    int end = g_rowoff[warp + 1];

    float2 acc = make_float2(0.f, 0.f);
    for (int e = beg; e < end; e += 32) {
        int idx = e + lane;
        int c = 0; float w = 0.f;
        if (idx < end) { c = g_ecol[idx]; w = g_ew[idx]; }
        int cnt = min(32, end - e);
        for (int j = 0; j < cnt; j++) {
            int   cc = __shfl_sync(0xffffffffu, c, j);
            float ww = __shfl_sync(0xffffffffu, w, j);
            float2 hv = *(const float2*)(hsrc + (size_t)cc * OUTD + lane * 2);
            acc.x = fmaf(hv.x, ww, acc.x);
            acc.y = fmaf(hv.y, ww, acc.y);
        }
    }
    float2 h0v = *(const float2*)(h0 + (size_t)warp * OUTD + lane * 2);
    float2 outv;
    outv.x = (1.0f - ALPHA) * acc.x + ALPHA * h0v.x;
    outv.y = (1.0f - ALPHA) * acc.y + ALPHA * h0v.y;
    *(float2*)(hdst + (size_t)warp * OUTD + lane * 2) = outv;
}

// ---------------- host launcher ----------------
extern "C" void kernel_launch(void* const* d_in, const int* in_sizes, int n_in,
                              void* d_out, int out_size)
{
    const float* x    = (const float*)d_in[0];
    const float* W1   = (const float*)d_in[1];
    const float* b1   = (const float*)d_in[2];
    const float* W2   = (const float*)d_in[3];
    const float* b2   = (const float*)d_in[4];
    const float* W3   = (const float*)d_in[5];
    const float* b3   = (const float*)d_in[6];
    const float* ew   = (const float*)d_in[7];
    const int*   erow = (const int*)d_in[8];
    const int*   ecol = (const int*)d_in[9];

    float *h1, *h2, *h0, *hA, *hB;
    __nv_bfloat16 *b1h, *b1l, *b2h, *b2l, *b3h, *b3l;
    cudaGetSymbolAddress((void**)&h1, g_h1);
    cudaGetSymbolAddress((void**)&h2, g_h2);
    cudaGetSymbolAddress((void**)&h0, g_h0);
    cudaGetSymbolAddress((void**)&hA, g_hA);
    cudaGetSymbolAddress((void**)&hB, g_hB);
    cudaGetSymbolAddress((void**)&b1h, g_B1h);
    cudaGetSymbolAddress((void**)&b1l, g_B1l);
    cudaGetSymbolAddress((void**)&b2h, g_B2h);
    cudaGetSymbolAddress((void**)&b2l, g_B2l);
    cudaGetSymbolAddress((void**)&b3h, g_B3h);
    cudaGetSymbolAddress((void**)&b3l, g_B3l);

    cudaFuncSetAttribute(gemm_mma_kernel<256, true >, cudaFuncAttributeMaxDynamicSharedMemorySize, GEMM_SMEM);
    cudaFuncSetAttribute(gemm_mma_kernel<64,  false>, cudaFuncAttributeMaxDynamicSharedMemorySize, GEMM_SMEM);

    // CSR build
    zero_cursor_kernel<<<NN / 256, 256>>>();
    hist_kernel<<<EE / 256, 256>>>(erow);
    scan_kernel<<<1, 1024>>>();
    scatter_kernel<<<EE / 256, 256>>>(erow, ecol, ew);

    // weight transpose + split
    splitw_kernel<<<(HID * KPAD1 + 255) / 256, 256>>>(W1, b1h, b1l, IN_DIM, HID, KPAD1);
    splitw_kernel<<<(HID * HID + 255) / 256, 256>>>(W2, b2h, b2l, HID, HID, HID);
    splitw_kernel<<<(OUTD * HID + 255) / 256, 256>>>(W3, b3h, b3l, HID, OUTD, HID);

    // MLP on tensor cores (bf16 2-term split, fp32 accumulate)
    gemm_mma_kernel<256, true ><<<dim3(NN / 128, 4), 256, GEMM_SMEM>>>(x,  b1h, b1l, b1, h1, IN_DIM, KPAD1);
    gemm_mma_kernel<256, true ><<<dim3(NN / 128, 4), 256, GEMM_SMEM>>>(h1, b2h, b2l, b2, h2, HID, HID);
    gemm_mma_kernel<64,  false><<<dim3(NN / 128, 1), 256, GEMM_SMEM>>>(h2, b3h, b3l, b3, h0, HID, HID);

    // K=10 propagation steps, final step writes d_out
    float* out = (float*)d_out;
    const float* src = h0;
    for (int s = 0; s < 10; s++) {
        float* dst = (s == 9) ? out : ((s & 1) ? hB : hA);
        prop_kernel<<<(NN * 32) / 256, 256>>>(src, h0, dst);
        src = dst;
    }
}

// round 4
// speedup vs baseline: 1.6369x; 1.0296x over previous
#include <cuda_runtime.h>
#include <cuda_bf16.h>
#include <cstdint>

#define NN      65536
#define EE      1048576
#define IN_DIM  500
#define KPAD1   512
#define HID     256
#define OUTD    64
#define ALPHA   0.1f

// ---------------- static device scratch ----------------
__device__ float g_h1[(size_t)NN * HID];
__device__ float g_h2[(size_t)NN * HID];
__device__ float g_h0[(size_t)NN * OUTD];
__device__ float g_hA[(size_t)NN * OUTD];
__device__ float g_hB[(size_t)NN * OUTD];
__device__ __nv_bfloat16 g_B1h[(size_t)HID * KPAD1];
__device__ __nv_bfloat16 g_B1l[(size_t)HID * KPAD1];
__device__ __nv_bfloat16 g_B2h[(size_t)HID * HID];
__device__ __nv_bfloat16 g_B2l[(size_t)HID * HID];
__device__ __nv_bfloat16 g_B3h[(size_t)OUTD * HID];
__device__ __nv_bfloat16 g_B3l[(size_t)OUTD * HID];
__device__ int   g_rowoff[NN + 1];
__device__ int   g_cursor[NN];
__device__ int2  g_edge[EE];     // (col, weight-bits)

// ---------------- helpers ----------------
__device__ __forceinline__ uint32_t smem_to_u32(const void* p) {
    uint32_t a;
    asm("{ .reg .u64 t; cvta.to.shared.u64 t, %1; cvt.u32.u64 %0, t; }" : "=r"(a) : "l"(p));
    return a;
}

__device__ __forceinline__ void ldmatrix_x4(uint32_t* r, uint32_t addr) {
    asm volatile("ldmatrix.sync.aligned.m8n8.x4.shared.b16 {%0,%1,%2,%3}, [%4];"
                 : "=r"(r[0]), "=r"(r[1]), "=r"(r[2]), "=r"(r[3]) : "r"(addr));
}

__device__ __forceinline__ void mma_bf16(float* c, const uint32_t* a, const uint32_t* b) {
    asm volatile(
        "mma.sync.aligned.m16n8k16.row.col.f32.bf16.bf16.f32 "
        "{%0,%1,%2,%3}, {%4,%5,%6,%7}, {%8,%9}, {%0,%1,%2,%3};"
        : "+f"(c[0]), "+f"(c[1]), "+f"(c[2]), "+f"(c[3])
        : "r"(a[0]), "r"(a[1]), "r"(a[2]), "r"(a[3]), "r"(b[0]), "r"(b[1]));
}

__device__ __forceinline__ void split_bf16(float a, __nv_bfloat16& hi, __nv_bfloat16& lo) {
    hi = __float2bfloat16_rn(a);
    lo = __float2bfloat16_rn(a - __bfloat162float(hi));
}
__device__ __forceinline__ uint32_t pack_bf16(__nv_bfloat16 x0, __nv_bfloat16 x1) {
    return ((uint32_t)__bfloat16_as_ushort(x1) << 16) | (uint32_t)__bfloat16_as_ushort(x0);
}

// ---------------- CSR construction ----------------
__global__ void zero_cursor_kernel() {
    int i = blockIdx.x * blockDim.x + threadIdx.x;
    if (i < NN) g_cursor[i] = 0;
}
__global__ void hist_kernel(const int* __restrict__ row) {
    int e = blockIdx.x * blockDim.x + threadIdx.x;
    if (e < EE) atomicAdd(&g_cursor[row[e]], 1);
}
__global__ void scan_kernel() {
    __shared__ int s[1024];
    int t = threadIdx.x;
    int base = t * 64;
    int sum = 0;
#pragma unroll 8
    for (int i = 0; i < 64; i++) sum += g_cursor[base + i];
    s[t] = sum;
    __syncthreads();
    for (int off = 1; off < 1024; off <<= 1) {
        int v = (t >= off) ? s[t - off] : 0;
        __syncthreads();
        s[t] += v;
        __syncthreads();
    }
    int running = s[t] - sum;
    for (int i = 0; i < 64; i++) {
        int d = g_cursor[base + i];
        g_rowoff[base + i] = running;
        g_cursor[base + i] = running;
        running += d;
    }
    if (t == 1023) g_rowoff[NN] = s[1023];
}
__global__ void scatter_kernel(const int* __restrict__ row, const int* __restrict__ col,
                               const float* __restrict__ w) {
    int e = blockIdx.x * blockDim.x + threadIdx.x;
    if (e < EE) {
        int p = atomicAdd(&g_cursor[row[e]], 1);
        g_edge[p] = make_int2(col[e], __float_as_int(w[e]));
    }
}

// ---------------- weight transpose + pad + bf16 split ----------------
__global__ void splitw_kernel(const float* __restrict__ W,
                              __nv_bfloat16* __restrict__ Bh, __nv_bfloat16* __restrict__ Bl,
                              int K, int N, int Kpad) {
    int idx = blockIdx.x * blockDim.x + threadIdx.x;
    if (idx >= N * Kpad) return;
    int n = idx / Kpad, k = idx - n * Kpad;
    float v = (k < K) ? W[(size_t)k * N + n] : 0.f;
    __nv_bfloat16 hi, lo;
    split_bf16(v, hi, lo);
    Bh[idx] = hi;
    Bl[idx] = lo;
}

// ---------------- bf16-split mma.sync GEMM ----------------
// CTA tile 128x64, BK=32, 8 warps 4(m)x2(n), warp tile 32x32. Double-buffered.
#define SM_AH   0
#define SM_AL   10240
#define SM_BH   20480
#define SM_BL   25600
#define SM_BUF  30720
#define GEMM_SMEM (2 * SM_BUF)

template <int N_, bool RELU>
__global__ void __launch_bounds__(256, 2) gemm_mma_kernel(
    const float* __restrict__ A, const __nv_bfloat16* __restrict__ Bh,
    const __nv_bfloat16* __restrict__ Bl, const float* __restrict__ bias,
    float* __restrict__ C, int K, int Kpad)
{
    extern __shared__ char smem[];
    uint32_t sbase = smem_to_u32(smem);

    int tid  = threadIdx.x;
    int wid  = tid >> 5;
    int lane = tid & 31;
    int m0 = blockIdx.x * 128;
    int n0 = blockIdx.y * 64;
    int warp_m = wid & 3;
    int warp_n = wid >> 2;

    float acc[2][4][4];
#pragma unroll
    for (int i = 0; i < 2; i++)
#pragma unroll
        for (int j = 0; j < 4; j++)
#pragma unroll
            for (int r = 0; r < 4; r++) acc[i][j][r] = 0.f;

    const int nch = Kpad >> 5;

    float4 ga[4];
    uint4  gbh, gbl;

    int a_row[4], a_col[4];
#pragma unroll
    for (int i = 0; i < 4; i++) {
        int slot = tid + i * 256;
        a_row[i] = slot >> 3;
        a_col[i] = (slot & 7) * 4;
    }
    int b_row = tid >> 2;
    int b_seg = tid & 3;

#define LOAD_GLOBAL(CH) do { \
    int k0_ = (CH) << 5; \
    _Pragma("unroll") \
    for (int i = 0; i < 4; i++) { \
        int kg = k0_ + a_col[i]; \
        if (kg < K) ga[i] = *(const float4*)(A + (size_t)(m0 + a_row[i]) * K + kg); \
        else        ga[i] = make_float4(0.f, 0.f, 0.f, 0.f); \
    } \
    { \
        const __nv_bfloat16* ph = Bh + (size_t)(n0 + b_row) * Kpad + k0_ + b_seg * 8; \
        const __nv_bfloat16* pl = Bl + (size_t)(n0 + b_row) * Kpad + k0_ + b_seg * 8; \
        gbh = *(const uint4*)ph; \
        gbl = *(const uint4*)pl; \
    } \
} while (0)

#define STORE_SMEM(BUF) do { \
    char* tb = smem + (BUF) * SM_BUF; \
    _Pragma("unroll") \
    for (int i = 0; i < 4; i++) { \
        __nv_bfloat16 hx, lx, hy, ly, hz, lz, hw, lw; \
        split_bf16(ga[i].x, hx, lx); split_bf16(ga[i].y, hy, ly); \
        split_bf16(ga[i].z, hz, lz); split_bf16(ga[i].w, hw, lw); \
        uint2 ph_ = make_uint2(pack_bf16(hx, hy), pack_bf16(hz, hw)); \
        uint2 pl_ = make_uint2(pack_bf16(lx, ly), pack_bf16(lz, lw)); \
        int off = a_row[i] * 80 + a_col[i] * 2; \
        *(uint2*)(tb + SM_AH + off) = ph_; \
        *(uint2*)(tb + SM_AL + off) = pl_; \
    } \
    { \
        int off = b_row * 80 + b_seg * 16; \
        *(uint4*)(tb + SM_BH + off) = gbh; \
        *(uint4*)(tb + SM_BL + off) = gbl; \
    } \
} while (0)

    LOAD_GLOBAL(0);
    STORE_SMEM(0);
    __syncthreads();

    for (int ch = 0; ch < nch; ch++) {
        if (ch + 1 < nch) LOAD_GLOBAL(ch + 1);

        uint32_t ub = sbase + (ch & 1) * SM_BUF;
#pragma unroll
        for (int kk = 0; kk < 32; kk += 16) {
            uint32_t afr[2][2][4];
            uint32_t bfr[2][2][4];
            {
                int rowA = warp_m * 32 + (lane & 15);
                int colA = kk + ((lane >> 4) << 3);
#pragma unroll
                for (int mt = 0; mt < 2; mt++) {
                    uint32_t ad = ub + (uint32_t)((rowA + mt * 16) * 80 + colA * 2);
                    ldmatrix_x4(afr[0][mt], ad + SM_AH);
                    ldmatrix_x4(afr[1][mt], ad + SM_AL);
                }
                int rowB = warp_n * 32 + ((lane >> 4) << 3) + (lane & 7);
                int colB = kk + (((lane >> 3) & 1) << 3);
#pragma unroll
                for (int np = 0; np < 2; np++) {
                    uint32_t bd = ub + (uint32_t)((rowB + np * 16) * 80 + colB * 2);
                    ldmatrix_x4(bfr[0][np], bd + SM_BH);
                    ldmatrix_x4(bfr[1][np], bd + SM_BL);
                }
            }
#pragma unroll
            for (int mt = 0; mt < 2; mt++)
#pragma unroll
                for (int nt = 0; nt < 4; nt++) {
                    int np = nt >> 1, sub = (nt & 1) * 2;
                    mma_bf16(acc[mt][nt], afr[0][mt], &bfr[0][np][sub]);
                    mma_bf16(acc[mt][nt], afr[0][mt], &bfr[1][np][sub]);
                    mma_bf16(acc[mt][nt], afr[1][mt], &bfr[0][np][sub]);
                }
        }
        __syncthreads();
        if (ch + 1 < nch) {
            STORE_SMEM((ch + 1) & 1);
        }
        __syncthreads();
    }

    int rb   = m0 + warp_m * 32 + (lane >> 2);
    int colb = n0 + warp_n * 32 + (lane & 3) * 2;
#pragma unroll
    for (int mt = 0; mt < 2; mt++)
#pragma unroll
        for (int nt = 0; nt < 4; nt++)
#pragma unroll
            for (int r = 0; r < 4; r++) {
                int row = rb + mt * 16 + ((r >> 1) << 3);
                int col = colb + nt * 8 + (r & 1);
                float v = acc[mt][nt][r] + __ldg(bias + col);
                if (RELU) v = fmaxf(v, 0.f);
                C[(size_t)row * N_ + col] = v;
            }
}

// ---------------- propagation: warp = row, two 16-lane halves, float4 channels ----------------
// hdst[r] = 0.9 * sum_e h[col(e)]*w(e) + 0.1 * h0[r]
__global__ void __launch_bounds__(256) prop_kernel(
    const float* __restrict__ hsrc, const float* __restrict__ h0,
    float* __restrict__ hdst)
{
    int warp = (blockIdx.x * blockDim.x + threadIdx.x) >> 5;
    if (warp >= NN) return;
    int lane = threadIdx.x & 31;
    int half = lane >> 4;          // 0/1: alternate edges
    int sub  = lane & 15;          // channel group: 4 floats each

    int beg = g_rowoff[warp];
    int end = g_rowoff[warp + 1];

    float4 acc = make_float4(0.f, 0.f, 0.f, 0.f);
    for (int idx = beg + half; idx < end; idx += 2) {
        int2 ed = g_edge[idx];                 // broadcast within half (8B)
        float w = __int_as_float(ed.y);
        float4 hv = *(const float4*)(hsrc + (size_t)ed.x * OUTD + sub * 4);
        acc.x = fmaf(hv.x, w, acc.x);
        acc.y = fmaf(hv.y, w, acc.y);
        acc.z = fmaf(hv.z, w, acc.z);
        acc.w = fmaf(hv.w, w, acc.w);
    }
    __syncwarp();
    // combine halves: lane L += lane L+16
    acc.x += __shfl_down_sync(0xffffffffu, acc.x, 16);
    acc.y += __shfl_down_sync(0xffffffffu, acc.y, 16);
    acc.z += __shfl_down_sync(0xffffffffu, acc.z, 16);
    acc.w += __shfl_down_sync(0xffffffffu, acc.w, 16);

    if (half == 0) {
        float4 h0v = *(const float4*)(h0 + (size_t)warp * OUTD + sub * 4);
        float4 outv;
        outv.x = (1.0f - ALPHA) * acc.x + ALPHA * h0v.x;
        outv.y = (1.0f - ALPHA) * acc.y + ALPHA * h0v.y;
        outv.z = (1.0f - ALPHA) * acc.z + ALPHA * h0v.z;
        outv.w = (1.0f - ALPHA) * acc.w + ALPHA * h0v.w;
        *(float4*)(hdst + (size_t)warp * OUTD + sub * 4) = outv;
    }
}

// ---------------- host launcher ----------------
extern "C" void kernel_launch(void* const* d_in, const int* in_sizes, int n_in,
                              void* d_out, int out_size)
{
    const float* x    = (const float*)d_in[0];
    const float* W1   = (const float*)d_in[1];
    const float* b1   = (const float*)d_in[2];
    const float* W2   = (const float*)d_in[3];
    const float* b2   = (const float*)d_in[4];
    const float* W3   = (const float*)d_in[5];
    const float* b3   = (const float*)d_in[6];
    const float* ew   = (const float*)d_in[7];
    const int*   erow = (const int*)d_in[8];
    const int*   ecol = (const int*)d_in[9];

    float *h1, *h2, *h0, *hA, *hB;
    __nv_bfloat16 *b1h, *b1l, *b2h, *b2l, *b3h, *b3l;
    cudaGetSymbolAddress((void**)&h1, g_h1);
    cudaGetSymbolAddress((void**)&h2, g_h2);
    cudaGetSymbolAddress((void**)&h0, g_h0);
    cudaGetSymbolAddress((void**)&hA, g_hA);
    cudaGetSymbolAddress((void**)&hB, g_hB);
    cudaGetSymbolAddress((void**)&b1h, g_B1h);
    cudaGetSymbolAddress((void**)&b1l, g_B1l);
    cudaGetSymbolAddress((void**)&b2h, g_B2h);
    cudaGetSymbolAddress((void**)&b2l, g_B2l);
    cudaGetSymbolAddress((void**)&b3h, g_B3h);
    cudaGetSymbolAddress((void**)&b3l, g_B3l);

    cudaFuncSetAttribute(gemm_mma_kernel<256, true >, cudaFuncAttributeMaxDynamicSharedMemorySize, GEMM_SMEM);
    cudaFuncSetAttribute(gemm_mma_kernel<64,  false>, cudaFuncAttributeMaxDynamicSharedMemorySize, GEMM_SMEM);

    // CSR build
    zero_cursor_kernel<<<NN / 256, 256>>>();
    hist_kernel<<<EE / 256, 256>>>(erow);
    scan_kernel<<<1, 1024>>>();
    scatter_kernel<<<EE / 256, 256>>>(erow, ecol, ew);

    // weight transpose + split
    splitw_kernel<<<(HID * KPAD1 + 255) / 256, 256>>>(W1, b1h, b1l, IN_DIM, HID, KPAD1);
    splitw_kernel<<<(HID * HID + 255) / 256, 256>>>(W2, b2h, b2l, HID, HID, HID);
    splitw_kernel<<<(OUTD * HID + 255) / 256, 256>>>(W3, b3h, b3l, HID, OUTD, HID);

    // MLP on tensor cores (bf16 2-term split, fp32 accumulate)
    gemm_mma_kernel<256, true ><<<dim3(NN / 128, 4), 256, GEMM_SMEM>>>(x,  b1h, b1l, b1, h1, IN_DIM, KPAD1);
    gemm_mma_kernel<256, true ><<<dim3(NN / 128, 4), 256, GEMM_SMEM>>>(h1, b2h, b2l, b2, h2, HID, HID);
    gemm_mma_kernel<64,  false><<<dim3(NN / 128, 1), 256, GEMM_SMEM>>>(h2, b3h, b3l, b3, h0, HID, HID);

    // K=10 propagation steps
    float* out = (float*)d_out;
    const float* src = h0;
    for (int s = 0; s < 10; s++) {
        float* dst = (s == 9) ? out : ((s & 1) ? hB : hA);
        prop_kernel<<<(NN * 32) / 256, 256>>>(src, h0, dst);
        src = dst;
    }
}